// round 4
// baseline (speedup 1.0000x reference)
#include <cuda_runtime.h>
#include <cstdint>

// Fixed shapes: B=8, H=W=512
#define BB 8
#define NN (512*512)          // 262144 pixels per row
#define PP (BB*NN)
#define THREADS 256
#define TILE 2048             // pixels per block for k_compute
#define BLKX (NN/TILE)        // 128
#define HTILE 16384           // pixels per block for k_hist (amortize smem hist)
#define HBLKX (NN/HTILE)      // 16
#define STILE 4096            // pixels per block for k_sum
#define SBLKX (NN/STILE)      // 64
#define EQCAP 8192
#define NB 2048               // histogram bins (11-bit digits)

// ---------------- device scratch ----------------
__device__ uint32_t g_keys[PP];     // 8 MB
__device__ uint32_t g_pl3[PP];      // 8 MB  loss3 with target packed in sign bit
__device__ uint32_t g_hist[BB*NB];
__device__ uint32_t g_prefix[BB];   // accumulates selected digits (bits [10,32))
__device__ int      g_kneed[BB];
__device__ int      g_eqcount[BB];
__device__ int      g_eqlist[BB*EQCAP];
__device__ double   g_sum_l3;
__device__ unsigned long long g_sum_tsel;
__device__ unsigned long long g_ttotal;

__device__ __forceinline__ uint32_t f2mono(float f) {
    uint32_t u = __float_as_uint(f);
    return (u & 0x80000000u) ? ~u : (u | 0x80000000u);
}

// Robust scalar read (f32 vs f64 sniff; true values are in (0,1)).
__device__ __forceinline__ double read_scalar(const void* p) {
    float f = *(const float*)p;
    if (f > 1e-6f && f < 1.0f) return (double)f;
    return *(const double*)p;
}

// 2-class log-softmax: 3 MUFU ops (exp, rcp, log).
__device__ __forceinline__ void sm2(float x0, float x1,
                                    float& lp0, float& lp1, float& p0, float& p1) {
    float d = x0 - x1;
    float t = __expf(fminf(-d, 80.0f));
    p0 = __fdividef(1.0f, 1.0f + t);
    p1 = t * p0;
    lp0 = __logf(p0);
    lp1 = lp0 - d;
}

__device__ __forceinline__ void pixel_loss(float a1, float c1, float a2, float c2,
                                           float a3, float c3, int t,
                                           float kdw, float w,
                                           float& loss, float& l3) {
    float lp10, lp11, p10, p11; sm2(a1, c1, lp10, lp11, p10, p11);
    float lp20, lp21, p20, p21; sm2(a2, c2, lp20, lp21, p20, p21);
    float lp30, lp31, p30, p31; sm2(a3, c3, lp30, lp31, p30, p31);
    float tf = (float)t;
    float om11 = 1.0f - p11, om10 = 1.0f - p10;
    float om21 = 1.0f - p21, om20 = 1.0f - p20;
    float om31 = 1.0f - p31, om30 = 1.0f - p30;
    float l1 = -tf * om11*om11*lp11 - (1.0f-tf) * om10*om10*lp10;
    float l2 = -tf * om21*om21*lp21 - (1.0f-tf) * om20*om20*lp20;
    l3       = -tf * om31*om31*lp31 - (1.0f-tf) * om30*om30*lp30;
    float kdl12 = p10*(lp10-lp20) + p11*(lp11-lp21);
    float kdl21 = p20*(lp20-lp10) + p21*(lp21-lp11);
    loss = w * (l1 + l2 + l3) + kdw * (kdl12 + kdl21);
}

// ---------------- kernels ----------------

__global__ void k_init(const void* forget) {
    int tid = threadIdx.x + blockIdx.x * blockDim.x;
    if (blockIdx.x == 0) {
        double rem = 1.0 - read_scalar(forget);
        int num_rem = (int)(rem * (double)NN);
        if (threadIdx.x < BB) {
            g_kneed[threadIdx.x]   = num_rem;
            g_prefix[threadIdx.x]  = 0u;
            g_eqcount[threadIdx.x] = 0;
        }
        if (threadIdx.x == 0) { g_sum_l3 = 0.0; g_sum_tsel = 0ull; g_ttotal = 0ull; }
    }
    for (int i = tid; i < BB*NB; i += gridDim.x * blockDim.x) g_hist[i] = 0u;
}

// Fused math + key/payload store + 2048-bin histogram (top 11 bits) + target total.
__global__ void __launch_bounds__(THREADS)
k_compute(const float* __restrict__ in1, const float* __restrict__ in2,
          const float* __restrict__ in3, const int* __restrict__ tgt,
          const void* __restrict__ kdw_p)
{
    __shared__ uint32_t sh[NB];
    int tid = threadIdx.x;
#pragma unroll
    for (int i = 0; i < NB/THREADS; i++) sh[tid + i*THREADS] = 0u;
    __syncthreads();

    const int row = blockIdx.y;
    const float kdw = (float)read_scalar(kdw_p);
    const float w   = 1.0f - kdw;

    const float4* b1a = (const float4*)(in1 + (size_t)row * 2 * NN);
    const float4* b1c = (const float4*)(in1 + (size_t)row * 2 * NN + NN);
    const float4* b2a = (const float4*)(in2 + (size_t)row * 2 * NN);
    const float4* b2c = (const float4*)(in2 + (size_t)row * 2 * NN + NN);
    const float4* b3a = (const float4*)(in3 + (size_t)row * 2 * NN);
    const float4* b3c = (const float4*)(in3 + (size_t)row * 2 * NN + NN);
    const int4*   bt  = (const int4*)(tgt + (size_t)row * NN);
    uint4* kout = (uint4*)(g_keys + (size_t)row * NN);
    uint4* pout = (uint4*)(g_pl3  + (size_t)row * NN);

    int tcnt = 0;

#pragma unroll
    for (int g = 0; g < 2; g++) {
        int vi = (blockIdx.x * TILE + g * (TILE/2)) / 4 + tid;
        float4 A1 = b1a[vi], C1 = b1c[vi];
        float4 A2 = b2a[vi], C2 = b2c[vi];
        float4 A3 = b3a[vi], C3 = b3c[vi];
        int4   T  = bt[vi];

        float ls0, ls1, ls2, ls3, l30, l31, l32, l33;
        pixel_loss(A1.x, C1.x, A2.x, C2.x, A3.x, C3.x, T.x, kdw, w, ls0, l30);
        pixel_loss(A1.y, C1.y, A2.y, C2.y, A3.y, C3.y, T.y, kdw, w, ls1, l31);
        pixel_loss(A1.z, C1.z, A2.z, C2.z, A3.z, C3.z, T.z, kdw, w, ls2, l32);
        pixel_loss(A1.w, C1.w, A2.w, C2.w, A3.w, C3.w, T.w, kdw, w, ls3, l33);

        uint4 K = make_uint4(f2mono(ls0), f2mono(ls1), f2mono(ls2), f2mono(ls3));
        kout[vi] = K;
        uint4 P = make_uint4(__float_as_uint(l30) | ((uint32_t)T.x << 31),
                             __float_as_uint(l31) | ((uint32_t)T.y << 31),
                             __float_as_uint(l32) | ((uint32_t)T.z << 31),
                             __float_as_uint(l33) | ((uint32_t)T.w << 31));
        pout[vi] = P;

        atomicAdd(&sh[K.x >> 21], 1u);
        atomicAdd(&sh[K.y >> 21], 1u);
        atomicAdd(&sh[K.z >> 21], 1u);
        atomicAdd(&sh[K.w >> 21], 1u);
        tcnt += T.x + T.y + T.z + T.w;
    }
    __syncthreads();
#pragma unroll
    for (int i = 0; i < NB/THREADS; i++) {
        uint32_t v = sh[tid + i*THREADS];
        if (v) atomicAdd(&g_hist[row * NB + tid + i*THREADS], v);
    }

#pragma unroll
    for (int o = 16; o; o >>= 1) tcnt += __shfl_down_sync(0xffffffffu, tcnt, o);
    __shared__ int swt[8];
    if ((tid & 31) == 0) swt[tid >> 5] = tcnt;
    __syncthreads();
    if (tid == 0) {
        int s = 0;
#pragma unroll
        for (int i = 0; i < 8; i++) s += swt[i];
        atomicAdd(&g_ttotal, (unsigned long long)s);
    }
}

// One block per row: find the bin containing the kneed-th element,
// update prefix/kneed, zero the hist region for the next pass.
__global__ void k_select(int shift) {
    int row = blockIdx.x;
    int tid = threadIdx.x;
    const int per = NB / 256;             // 8 bins per thread
    uint32_t* h = g_hist + row * NB;
    unsigned kneed = (unsigned)g_kneed[row];

    unsigned local[8];
    unsigned lsum = 0;
#pragma unroll
    for (int i = 0; i < per; i++) { local[i] = h[tid * per + i]; lsum += local[i]; }

    __shared__ unsigned ss[256];
    ss[tid] = lsum;
    __syncthreads();
    for (int off = 1; off < 256; off <<= 1) {
        unsigned n = (tid >= off) ? ss[tid - off] : 0u;
        __syncthreads();
        ss[tid] += n;
        __syncthreads();
    }
    unsigned incl = ss[tid];
    unsigned excl = incl - lsum;

    if (excl < kneed && kneed <= incl) {
        unsigned cum = excl;
#pragma unroll
        for (int i = 0; i < per; i++) {
            if (cum + local[i] >= kneed) {
                g_prefix[row] |= ((uint32_t)(tid * per + i)) << shift;
                g_kneed[row]   = (int)(kneed - cum);
                break;
            }
            cum += local[i];
        }
    }
#pragma unroll
    for (int i = 0; i < per; i++) h[tid * per + i] = 0u;
}

// Histogram of 11-bit digit at bits [10,21), filtered by top-11-bit prefix.
// Large tiles: 16384 keys/block to amortize the smem histogram.
__global__ void __launch_bounds__(THREADS)
k_hist() {
    __shared__ uint32_t sh[NB];
    int tid = threadIdx.x;
#pragma unroll
    for (int i = 0; i < NB/THREADS; i++) sh[tid + i*THREADS] = 0u;
    __syncthreads();

    int row = blockIdx.y;
    uint32_t pfx = g_prefix[row] >> 21;
    const uint4* keys = (const uint4*)(g_keys + (size_t)row * NN);

#pragma unroll 4
    for (int it = 0; it < HTILE/(THREADS*4); it++) {
        int vi = blockIdx.x * (HTILE/4) + it * THREADS + tid;
        uint4 K = keys[vi];
        uint32_t ks[4] = {K.x, K.y, K.z, K.w};
#pragma unroll
        for (int j = 0; j < 4; j++)
            if ((ks[j] >> 21) == pfx)
                atomicAdd(&sh[(ks[j] >> 10) & 2047u], 1u);
    }
    __syncthreads();
#pragma unroll
    for (int i = 0; i < NB/THREADS; i++) {
        uint32_t v = sh[tid + i*THREADS];
        if (v) atomicAdd(&g_hist[row * NB + tid + i*THREADS], v);
    }
}

// Sum loss3/targets for keys strictly below the 22-bit bin; collect the whole
// bin (expected ~tens of elements) as "ties" for exact resolution in k_final.
__global__ void __launch_bounds__(THREADS)
k_sum() {
    int tid = threadIdx.x;
    int row = blockIdx.y;
    uint32_t thr = g_prefix[row];         // bits [10,32) set, low 10 bits zero
    uint32_t pfx22 = thr >> 10;
    const uint4* keys = (const uint4*)(g_keys + (size_t)row * NN);
    const uint4* pl3  = (const uint4*)(g_pl3  + (size_t)row * NN);

    float sl = 0.0f;
    int   st = 0;
    double sld = 0.0;

#pragma unroll 2
    for (int it = 0; it < STILE/(THREADS*4); it++) {
        int vi = blockIdx.x * (STILE/4) + it * THREADS + tid;
        uint4 K = keys[vi];
        uint4 P = pl3[vi];
        uint32_t ks[4] = {K.x, K.y, K.z, K.w};
        uint32_t ps[4] = {P.x, P.y, P.z, P.w};
#pragma unroll
        for (int j = 0; j < 4; j++) {
            if (ks[j] < thr) {
                sl += __uint_as_float(ps[j] & 0x7fffffffu);
                st += (int)(ps[j] >> 31);
            } else if ((ks[j] >> 10) == pfx22) {
                int p = atomicAdd(&g_eqcount[row], 1);
                if (p < EQCAP) g_eqlist[row * EQCAP + p] = vi * 4 + j;
            }
        }
        sld += (double)sl; sl = 0.0f;   // bound f32 accumulation error per tile
    }
#pragma unroll
    for (int o = 16; o; o >>= 1) {
        sld += __shfl_down_sync(0xffffffffu, sld, o);
        st  += __shfl_down_sync(0xffffffffu, st, o);
    }
    __shared__ double sd[8];
    __shared__ int    si[8];
    if ((tid & 31) == 0) { sd[tid >> 5] = sld; si[tid >> 5] = st; }
    __syncthreads();
    if (tid == 0) {
        double S = 0.0; int Ti = 0;
#pragma unroll
        for (int i = 0; i < 8; i++) { S += sd[i]; Ti += si[i]; }
        atomicAdd(&g_sum_l3, S);
        atomicAdd(&g_sum_tsel, (unsigned long long)Ti);
    }
}

// Rank-select within the 22-bit bin by (key, idx) lexicographic order
// (== stable argsort tie-break), accumulate the first kneed, write outputs.
__global__ void k_final(const void* __restrict__ forget, float* __restrict__ out) {
    int tid = threadIdx.x;
    for (int row = 0; row < BB; row++) {
        int m = g_kneed[row];
        int c = min(g_eqcount[row], EQCAP);
        for (int j = tid; j < c; j += blockDim.x) {
            int idx = g_eqlist[row * EQCAP + j];
            uint32_t kj = g_keys[(size_t)row * NN + idx];
            int rank = 0;
            for (int q = 0; q < c; q++) {
                int idq = g_eqlist[row * EQCAP + q];
                uint32_t kq = g_keys[(size_t)row * NN + idq];
                rank += (kq < kj || (kq == kj && idq < idx)) ? 1 : 0;
            }
            if (rank < m) {
                uint32_t p = g_pl3[(size_t)row * NN + idx];
                atomicAdd(&g_sum_l3, (double)__uint_as_float(p & 0x7fffffffu));
                atomicAdd(&g_sum_tsel, (unsigned long long)(p >> 31));
            }
        }
    }
    __threadfence();
    __syncthreads();
    if (tid == 0) {
        double sl = atomicAdd(&g_sum_l3, 0.0);
        unsigned long long ts = atomicAdd(&g_sum_tsel, 0ull);
        unsigned long long tt = atomicAdd(&g_ttotal, 0ull);
        double rem = 1.0 - read_scalar(forget);
        long long num_rem = (long long)(rem * (double)NN);
        double denom = (double)BB * (double)num_rem;
        out[0] = (float)(sl / denom);
        out[1] = (float)((double)ts / (double)tt);
    }
}

// ---------------- host entry ----------------
extern "C" void kernel_launch(void* const* d_in, const int* in_sizes, int n_in,
                              void* d_out, int out_size) {
    const float* in1    = (const float*)d_in[0];
    const float* in2    = (const float*)d_in[1];
    const float* in3    = (const float*)d_in[2];
    const int*   tgt    = (const int*)d_in[3];
    const void*  forget = d_in[4];
    const void*  kdw    = d_in[5];
    float* out = (float*)d_out;

    k_init<<<16, 256>>>(forget);
    k_compute<<<dim3(BLKX, BB), THREADS>>>(in1, in2, in3, tgt, kdw);
    k_select<<<BB, 256>>>(21);                       // digit A: bits [21,32)
    k_hist<<<dim3(HBLKX, BB), THREADS>>>();          // digit B: bits [10,21)
    k_select<<<BB, 256>>>(10);
    k_sum<<<dim3(SBLKX, BB), THREADS>>>();
    k_final<<<1, 256>>>(forget, out);

    (void)in_sizes; (void)n_in; (void)out_size;
}